// round 1
// baseline (speedup 1.0000x reference)
#include <cuda_runtime.h>
#include <cuda_bf16.h>

// JointBilateral upsample (PAC-style), S=4, K=5, PAD=1, OP=1.
// x:        (4,1,128,128) fp32   d_in[0]
// guidance: (4,3,512,512) fp32   d_in[1]
// weight:   (1,1,5,5)     fp32   d_in[2]
// out:      (4,1,512,512) fp32
//
// Per output pixel (b,h,w): active taps i satisfy (h+i-3)%4==0.
// First candidate i0=(3-h)&3 is always valid with low-res row ky=h>>2.
// Second candidate i0+4 valid iff (h&3)==3 && h<=507, ky=h>>2+1.
// Same along w. Kernel weight = exp(-0.5*(||0.5*dg||^2 + ((i-2)^2+(j-2)^2)*0.01)).
// norm = sum of exps; numerator additionally multiplied by weight[0,0,4-i,4-j].

#define HW 512
#define CH_STRIDE (512 * 512)
#define LR 128

__global__ void __launch_bounds__(256) jb_kernel(
    const float* __restrict__ x,
    const float* __restrict__ g,
    const float* __restrict__ wgt,
    float* __restrict__ out)
{
    int idx = blockIdx.x * blockDim.x + threadIdx.x;
    // total = 4*512*512 = 1048576, grid sized exactly
    int w = idx & (HW - 1);
    int h = (idx >> 9) & (HW - 1);
    int b = idx >> 18;

    const float* gb = g + (size_t)b * 3 * CH_STRIDE;
    const float* xb = x + (size_t)b * LR * LR;

    int center = h * HW + w;
    float g0 = gb[center] * 0.5f;
    float g1 = gb[center + CH_STRIDE] * 0.5f;
    float g2 = gb[center + 2 * CH_STRIDE] * 0.5f;

    int i0 = (3 - h) & 3;
    int j0 = (3 - w) & 3;
    int ni = ((h & 3) == 3 && h <= 507) ? 2 : 1;
    int nj = ((w & 3) == 3 && w <= 507) ? 2 : 1;
    int kyb = h >> 2;
    int kxb = w >> 2;

    float acc = 0.0f;
    float norm = 0.0f;

#pragma unroll
    for (int ti = 0; ti < 2; ti++) {
        if (ti >= ni) break;
        int i = i0 + 4 * ti;
        int y = h + i - 2;               // guidance row, in [1,509]
        float spi = (float)((i - 2) * (i - 2));
        int grow = y * HW;
        const float* xr = xb + (kyb + ti) * LR;
#pragma unroll
        for (int tj = 0; tj < 2; tj++) {
            if (tj >= nj) break;
            int j = j0 + 4 * tj;
            int xg = w + j - 2;          // guidance col, in [1,509]
            int off = grow + xg;
            float d0 = __ldg(&gb[off]) * 0.5f - g0;
            float d1 = __ldg(&gb[off + CH_STRIDE]) * 0.5f - g1;
            float d2 = __ldg(&gb[off + 2 * CH_STRIDE]) * 0.5f - g2;
            float sp = (spi + (float)((j - 2) * (j - 2))) * 0.01f;
            float e = __expf(-0.5f * (d0 * d0 + d1 * d1 + d2 * d2 + sp));
            norm += e;
            // conv-transpose weight, transposed + flipped: weight[0,0,4-i,4-j]
            float wv = __ldg(&wgt[(4 - i) * 5 + (4 - j)]);
            acc += e * wv * __ldg(&xr[kxb + tj]);
        }
    }

    // norm > 0 always (exp of finite arg, >=1 tap); guard anyway
    out[idx] = acc / (norm + (norm == 0.0f ? 1.0f : 0.0f));
}

extern "C" void kernel_launch(void* const* d_in, const int* in_sizes, int n_in,
                              void* d_out, int out_size)
{
    const float* x   = (const float*)d_in[0];
    const float* g   = (const float*)d_in[1];
    const float* wgt = (const float*)d_in[2];
    float* out = (float*)d_out;

    int total = out_size;                 // 4*512*512 = 1048576
    int threads = 256;
    int blocks = (total + threads - 1) / threads;  // 4096
    jb_kernel<<<blocks, threads>>>(x, g, wgt, out);
}

// round 2
// speedup vs baseline: 1.1964x; 1.1964x over previous
#include <cuda_runtime.h>
#include <cuda_bf16.h>

// JointBilateral upsample, S=4, K=5. One thread computes 4 horizontal output
// pixels (w = 4q..4q+3). All 4 share the first tap guidance column 4q+1 and
// tap row 4p+1; second row tap exists iff h%4==3 && h<=507; second col tap
// exists only for the r=3 pixel iff q<127.
//
// e(tap) = exp(-0.5*||0.5*(g_tap - g_ctr)||^2) * exp(-0.005*((i-2)^2+(j-2)^2))
// out = sum(e * wgt[4-i][4-j] * x_tap) / sum(e)
// First-tap weight indices simplify: row = s+1, col = r+1; second row/col -> 0.

#define CH  (512 * 512)
#define E1  0.9950124791926823f   /* exp(-0.005) */
#define E4  0.9801986733067553f   /* exp(-0.020) */

__global__ void __launch_bounds__(256) jb_kernel(
    const float* __restrict__ x,
    const float* __restrict__ g,
    const float* __restrict__ wgt,
    float* __restrict__ out)
{
    int idx = blockIdx.x * 256 + threadIdx.x;   // 262144 threads total
    int q = idx & 127;
    int h = (idx >> 7) & 511;
    int b = idx >> 16;

    const float* gb = g + (size_t)b * 3 * CH;
    const float* xb = x + b * (128 * 128);

    int w0 = q << 2;
    int p  = h >> 2;
    int s  = h & 3;

    // centers (scaled by 0.5)
    float4 c0 = *(const float4*)(gb + h * 512 + w0);
    float4 c1 = *(const float4*)(gb + CH + h * 512 + w0);
    float4 c2 = *(const float4*)(gb + 2 * CH + h * 512 + w0);
    c0.x *= 0.5f; c0.y *= 0.5f; c0.z *= 0.5f; c0.w *= 0.5f;
    c1.x *= 0.5f; c1.y *= 0.5f; c1.z *= 0.5f; c1.w *= 0.5f;
    c2.x *= 0.5f; c2.y *= 0.5f; c2.z *= 0.5f; c2.w *= 0.5f;

    bool row2 = (s == 3) && (p < 127);
    bool col2 = (q < 127);

    int y0  = 4 * p + 1;
    int x0c = 4 * q + 1;
    int o00 = y0 * 512 + x0c;

    // tap guidance values (scaled by 0.5): t[row][col][chan]
    float t000 = __ldg(gb + o00)          * 0.5f;
    float t001 = __ldg(gb + o00 + CH)     * 0.5f;
    float t002 = __ldg(gb + o00 + 2 * CH) * 0.5f;

    float t010 = 0.f, t011 = 0.f, t012 = 0.f;
    if (col2) {
        t010 = __ldg(gb + o00 + 4)          * 0.5f;
        t011 = __ldg(gb + o00 + 4 + CH)     * 0.5f;
        t012 = __ldg(gb + o00 + 4 + 2 * CH) * 0.5f;
    }
    float t100 = 0.f, t101 = 0.f, t102 = 0.f;
    float t110 = 0.f, t111 = 0.f, t112 = 0.f;
    if (row2) {
        int o10 = o00 + 4 * 512;
        t100 = __ldg(gb + o10)          * 0.5f;
        t101 = __ldg(gb + o10 + CH)     * 0.5f;
        t102 = __ldg(gb + o10 + 2 * CH) * 0.5f;
        if (col2) {
            t110 = __ldg(gb + o10 + 4)          * 0.5f;
            t111 = __ldg(gb + o10 + 4 + CH)     * 0.5f;
            t112 = __ldg(gb + o10 + 4 + 2 * CH) * 0.5f;
        }
    }

    // low-res x values
    int qq = col2 ? q + 1 : q;
    int pp = row2 ? p + 1 : p;
    float x00 = __ldg(xb + p * 128 + q);
    float x01 = __ldg(xb + p * 128 + qq);
    float x10 = __ldg(xb + pp * 128 + q);
    float x11 = __ldg(xb + pp * 128 + qq);

    // conv-transpose weights: first-tap row index = s+1, second row = 0
    float wr0 = __ldg(wgt + (s + 1) * 5 + 0);
    float wr1 = __ldg(wgt + (s + 1) * 5 + 1);
    float wr2 = __ldg(wgt + (s + 1) * 5 + 2);
    float wr3 = __ldg(wgt + (s + 1) * 5 + 3);
    float wr4 = __ldg(wgt + (s + 1) * 5 + 4);
    float v0  = __ldg(wgt + 0);
    float v1  = __ldg(wgt + 1);
    float v2  = __ldg(wgt + 2);
    float v3  = __ldg(wgt + 3);
    float v4  = __ldg(wgt + 4);

    // spatial exp factor for the first tap row: (i0-2)^2 = {1,0,1,4} for s=0..3
    float espR0 = (s == 1) ? 1.0f : ((s == 3) ? E4 : E1);

    float res[4];
    const float espC[4] = {E1, 1.0f, E1, E4};   // first-tap col spatial factor per r
    const float wcF[4]  = {wr1, wr2, wr3, wr4}; // first-row weight, col r+1
    const float wcS[4]  = {v1, v2, v3, v4};     // second-row weight, col r+1
    float ctr0[4] = {c0.x, c0.y, c0.z, c0.w};
    float ctr1[4] = {c1.x, c1.y, c1.z, c1.w};
    float ctr2[4] = {c2.x, c2.y, c2.z, c2.w};

#pragma unroll
    for (int r = 0; r < 4; r++) {
        float d0 = t000 - ctr0[r];
        float d1 = t001 - ctr1[r];
        float d2 = t002 - ctr2[r];
        float e  = __expf(-0.5f * (d0 * d0 + d1 * d1 + d2 * d2)) * espR0 * espC[r];
        float n  = e;
        float a  = e * wcF[r] * x00;

        if (row2) {
            float f0 = t100 - ctr0[r];
            float f1 = t101 - ctr1[r];
            float f2 = t102 - ctr2[r];
            float e2 = __expf(-0.5f * (f0 * f0 + f1 * f1 + f2 * f2)) * E4 * espC[r];
            n += e2;
            a += e2 * wcS[r] * x10;
        }
        if (r == 3 && col2) {
            float h0 = t010 - ctr0[r];
            float h1 = t011 - ctr1[r];
            float h2 = t012 - ctr2[r];
            float e3 = __expf(-0.5f * (h0 * h0 + h1 * h1 + h2 * h2)) * espR0 * E4;
            n += e3;
            a += e3 * wr0 * x01;
            if (row2) {
                float k0 = t110 - ctr0[r];
                float k1 = t111 - ctr1[r];
                float k2 = t112 - ctr2[r];
                float e4 = __expf(-0.5f * (k0 * k0 + k1 * k1 + k2 * k2)) * E4 * E4;
                n += e4;
                a += e4 * v0 * x11;
            }
        }
        res[r] = __fdividef(a, n);
    }

    float4 o = make_float4(res[0], res[1], res[2], res[3]);
    *(float4*)(out + (size_t)idx * 4) = o;
}

extern "C" void kernel_launch(void* const* d_in, const int* in_sizes, int n_in,
                              void* d_out, int out_size)
{
    const float* x   = (const float*)d_in[0];
    const float* g   = (const float*)d_in[1];
    const float* wgt = (const float*)d_in[2];
    float* out = (float*)d_out;

    int total_threads = out_size / 4;     // 262144
    jb_kernel<<<total_threads / 256, 256>>>(x, g, wgt, out);
}